// round 1
// baseline (speedup 1.0000x reference)
#include <cuda_runtime.h>
#include <math.h>

#define FULL 0xffffffffu

static constexpr int B_   = 256;
static constexpr int D_   = 128;
static constexpr int DIN_ = 2048;
static constexpr int M_   = 4096;
static constexpr float TAU_INV = 1.0f / 0.07f;

// ---------------- device scratch (no allocations allowed) ----------------
__device__ float  g_Wt[DIN_ * D_];              // W transposed: [k][d], 1 MB
__device__ float4 g_part[32 * B_ * (D_ / 4)];   // 32 K-slices of partial GEMM, 4 MB
__device__ float4 g_emb[B_ * (D_ / 4)];         // normalized embeddings, 128 KB
__device__ float  g_acc[2];                     // [0]=sum data softplus, [1]=sum noise softplus

// ---------------- A0: transpose W (D x DIN -> DIN x D), zero accumulators ----
__global__ void kTranspose(const float* __restrict__ W) {
    __shared__ float t[32][33];
    int k0 = blockIdx.x * 32, d0 = blockIdx.y * 32;
    int tx = threadIdx.x, ty = threadIdx.y;
#pragma unroll
    for (int i = ty; i < 32; i += 8)
        t[i][tx] = W[(size_t)(d0 + i) * DIN_ + k0 + tx];
    __syncthreads();
#pragma unroll
    for (int i = ty; i < 32; i += 8)
        g_Wt[(size_t)(k0 + i) * D_ + d0 + tx] = t[tx][i];
    if (blockIdx.x == 0 && blockIdx.y == 0 && tx == 0 && ty == 0) {
        g_acc[0] = 0.0f;
        g_acc[1] = 0.0f;
    }
}

// ---------------- A1: split-K partial GEMM: emb_raw = outputs @ W^T ----------
// grid 128 = 32 b-groups (of 8 rows) x 4 K-splits (of 512). 256 threads = 8 warps,
// each warp owns a 64-wide K sub-slice; lanes cover all 128 D via float4.
__global__ void __launch_bounds__(256) kGemmPart(const float* __restrict__ outputs) {
    int bg = blockIdx.x & 31;
    int ks = blockIdx.x >> 5;   // 0..3
    __shared__ float so[8][512];

    int tid = threadIdx.x;
    const float4* o4 = (const float4*)outputs;
#pragma unroll
    for (int i = tid; i < 1024; i += 256) {
        int bb = i >> 7, c = i & 127;
        ((float4*)so[bb])[c] = o4[(size_t)(bg * 8 + bb) * (DIN_ / 4) + ks * 128 + c];
    }
    __syncthreads();

    int w = tid >> 5, lane = tid & 31;
    float4 acc[8];
#pragma unroll
    for (int bb = 0; bb < 8; bb++) acc[bb] = make_float4(0.f, 0.f, 0.f, 0.f);

    const float4* wt4 = (const float4*)g_Wt;
    int kglob = ks * 512 + w * 64;
    int kloc  = w * 64;
#pragma unroll 4
    for (int kk = 0; kk < 64; kk++) {
        float4 wv = wt4[(size_t)(kglob + kk) * 32 + lane];
#pragma unroll
        for (int bb = 0; bb < 8; bb++) {
            float a = so[bb][kloc + kk];
            acc[bb].x = fmaf(a, wv.x, acc[bb].x);
            acc[bb].y = fmaf(a, wv.y, acc[bb].y);
            acc[bb].z = fmaf(a, wv.z, acc[bb].z);
            acc[bb].w = fmaf(a, wv.w, acc[bb].w);
        }
    }
    int slice = ks * 8 + w;   // 0..31
#pragma unroll
    for (int bb = 0; bb < 8; bb++) {
        int b = bg * 8 + bb;
        g_part[(size_t)slice * (B_ * 32) + b * 32 + lane] = acc[bb];
    }
}

// ---------------- A2: combine partials, add bias, L2-normalize -> g_emb -----
__global__ void kCombineNorm(const float* __restrict__ bias) {
    int b = blockIdx.x, lane = threadIdx.x;
    float4 s = make_float4(0.f, 0.f, 0.f, 0.f);
#pragma unroll
    for (int p = 0; p < 32; p++) {
        float4 v = g_part[(size_t)p * (B_ * 32) + b * 32 + lane];
        s.x += v.x; s.y += v.y; s.z += v.z; s.w += v.w;
    }
    float4 bv = ((const float4*)bias)[lane];
    s.x += bv.x; s.y += bv.y; s.z += bv.z; s.w += bv.w;
    float nsq = s.x * s.x + s.y * s.y + s.z * s.z + s.w * s.w;
#pragma unroll
    for (int o = 16; o; o >>= 1) nsq += __shfl_xor_sync(FULL, nsq, o);
    float inv = 1.0f / fmaxf(sqrtf(nsq), 1e-12f);
    s.x *= inv; s.y *= inv; s.z *= inv; s.w *= inv;
    g_emb[b * 32 + lane] = s;
}

// ---------------- B: main gather + logsumexp + losses + entries --------------
// One block per batch row. 16 warps; warp w handles negs [w*256, w*256+256).
__global__ void __launch_bounds__(512, 2) kMain(
    const float* __restrict__ mbank,
    const int*   __restrict__ indices,
    const int*   __restrict__ ridx,
    float*       __restrict__ out) {
    int b = blockIdx.x;
    int tid = threadIdx.x, w = tid >> 5, lane = tid & 31;

    __shared__ float sneg[M_];
    __shared__ float sr[33];

    float4 e = g_emb[b * 32 + lane];
    const float4* mb4 = (const float4*)mbank;
    const int* ri = ridx + (size_t)b * M_;

    // ---- gather + dot: 256 negs per warp ----
    int m0 = w * 256;
    for (int mb_ = m0; mb_ < m0 + 256; mb_ += 32) {
        int myIdx = ri[mb_ + lane];
#pragma unroll 8
        for (int j = 0; j < 32; j++) {
            int idx = __shfl_sync(FULL, myIdx, j);
            float4 v = mb4[(size_t)idx * 32 + lane];
            float d = v.x * e.x + v.y * e.y;
            d = fmaf(v.z, e.z, d);
            d = fmaf(v.w, e.w, d);
#pragma unroll
            for (int o = 16; o; o >>= 1) d += __shfl_xor_sync(FULL, d, o);
            if (lane == j) sneg[mb_ + j] = d * TAU_INV;
        }
    }
    __syncthreads();

    // ---- each thread owns 8 negs (bank-conflict-free stride 512) ----
    float vl[8];
    float mx = -3.0e38f;
#pragma unroll
    for (int i = 0; i < 8; i++) {
        vl[i] = sneg[tid + i * 512];
        mx = fmaxf(mx, vl[i]);
    }
    // block max
#pragma unroll
    for (int o = 16; o; o >>= 1) mx = fmaxf(mx, __shfl_xor_sync(FULL, mx, o));
    if (lane == 0) sr[w] = mx;
    __syncthreads();
    if (w == 0) {
        float t2 = sr[lane & 15];
#pragma unroll
        for (int o = 8; o; o >>= 1) t2 = fmaxf(t2, __shfl_xor_sync(FULL, t2, o));
        if (lane == 0) sr[32] = t2;
    }
    __syncthreads();
    float Mx = sr[32];

    // block sum of exp(v - Mx)
    float se = 0.f;
#pragma unroll
    for (int i = 0; i < 8; i++) se += __expf(vl[i] - Mx);
#pragma unroll
    for (int o = 16; o; o >>= 1) se += __shfl_xor_sync(FULL, se, o);
    __syncthreads();
    if (lane == 0) sr[w] = se;
    __syncthreads();
    if (w == 0) {
        float t2 = (lane < 16) ? sr[lane] : 0.f;
#pragma unroll
        for (int o = 8; o; o >>= 1) t2 += __shfl_xor_sync(FULL, t2, o);
        if (lane == 0) sr[32] = Mx + __logf(t2);
    }
    __syncthreads();
    float logC = sr[32];

    // noise loss: sum softplus(neg - logC)
    float ns = 0.f;
#pragma unroll
    for (int i = 0; i < 8; i++) {
        float x = vl[i] - logC;
        ns += (x > 15.f) ? x : log1pf(__expf(x));
    }
#pragma unroll
    for (int o = 16; o; o >>= 1) ns += __shfl_xor_sync(FULL, ns, o);
    __syncthreads();
    if (lane == 0) sr[w] = ns;
    __syncthreads();
    if (w == 0) {
        float t2 = (lane < 16) ? sr[lane] : 0.f;
#pragma unroll
        for (int o = 8; o; o >>= 1) t2 += __shfl_xor_sync(FULL, t2, o);
        if (lane == 0) atomicAdd(&g_acc[1], t2);
    }

    // ---- warp 0: positive term + entries ----
    if (w == 0) {
        int pidx = indices[b];
        float4 p = mb4[(size_t)pidx * 32 + lane];
        float d = p.x * e.x + p.y * e.y;
        d = fmaf(p.z, e.z, d);
        d = fmaf(p.w, e.w, d);
#pragma unroll
        for (int o = 16; o; o >>= 1) d += __shfl_xor_sync(FULL, d, o);
        float pos = d * TAU_INV;

        float4 ent;
        ent.x = 0.5f * (p.x + e.x);
        ent.y = 0.5f * (p.y + e.y);
        ent.z = 0.5f * (p.z + e.z);
        ent.w = 0.5f * (p.w + e.w);
        float nsq = ent.x * ent.x + ent.y * ent.y + ent.z * ent.z + ent.w * ent.w;
#pragma unroll
        for (int o = 16; o; o >>= 1) nsq += __shfl_xor_sync(FULL, nsq, o);
        float inv = 1.0f / fmaxf(sqrtf(nsq), 1e-12f);
        ent.x *= inv; ent.y *= inv; ent.z *= inv; ent.w *= inv;

        // entries live at out[1 .. 1+32768) -- not 16B aligned, scalar stores
        int base = 1 + b * D_ + lane * 4;
        out[base + 0] = ent.x;
        out[base + 1] = ent.y;
        out[base + 2] = ent.z;
        out[base + 3] = ent.w;

        if (lane == 0) {
            float x = logC - pos;
            float dl = (x > 15.f) ? x : log1pf(__expf(x));
            atomicAdd(&g_acc[0], dl);
        }
    }
}

// ---------------- C: finalize scalars ----------------------------------------
__global__ void kFinal(float* __restrict__ out) {
    float dl = g_acc[0] * (1.0f / (float)B_);
    float nl = g_acc[1] * (1.0f / (float)B_);
    out[0] = dl + nl;
    out[1 + B_ * D_]     = dl;
    out[1 + B_ * D_ + 1] = nl;
}

// ---------------- launcher ----------------------------------------------------
extern "C" void kernel_launch(void* const* d_in, const int* in_sizes, int n_in,
                              void* d_out, int out_size) {
    const float* outputs = (const float*)d_in[0];
    const float* W       = (const float*)d_in[1];
    const float* bias    = (const float*)d_in[2];
    const float* mbank   = (const float*)d_in[3];
    const int*   indices = (const int*)d_in[4];
    const int*   ridx    = (const int*)d_in[5];
    float* out = (float*)d_out;

    kTranspose<<<dim3(64, 4), dim3(32, 8)>>>(W);
    kGemmPart<<<128, 256>>>(outputs);
    kCombineNorm<<<256, 32>>>(bias);
    kMain<<<256, 512>>>(mbank, indices, ridx, out);
    kFinal<<<1, 1>>>(out);
}

// round 3
// speedup vs baseline: 1.0974x; 1.0974x over previous
#include <cuda_runtime.h>
#include <cstdint>
#include <math.h>

#define FULL 0xffffffffu

static constexpr int B_   = 256;
static constexpr int D_   = 128;
static constexpr int DIN_ = 2048;
static constexpr int M_   = 4096;
static constexpr float TAU_INV = 1.0f / 0.07f;

// ---------------- device scratch ----------------
__device__ float4 g_emb[B_ * (D_ / 4)];   // normalized embeddings, 128 KB
__device__ float  g_acc[2];               // [0]=sum data softplus, [1]=sum noise softplus

// ---------------- cluster helpers (raw PTX, sm_90+) ----------------
__device__ __forceinline__ void cluster_sync_() {
    asm volatile("barrier.cluster.arrive.aligned;" ::: "memory");
    asm volatile("barrier.cluster.wait.aligned;" ::: "memory");
}
__device__ __forceinline__ unsigned mapa_shared_(unsigned smem_addr, unsigned rank) {
    unsigned r;
    asm("mapa.shared::cluster.u32 %0, %1, %2;" : "=r"(r) : "r"(smem_addr), "r"(rank));
    return r;
}
__device__ __forceinline__ float ld_shared_cluster_f32_(unsigned addr) {
    float v;
    asm volatile("ld.shared::cluster.f32 %0, [%1];" : "=f"(v) : "r"(addr));
    return v;
}

// ---------------- A: fused GEMM + bias + L2-normalize (one kernel) ----------
// grid 128 = 32 b-groups (8 rows) x 4 d-groups (32 cols), cluster of 4 over d.
// 256 threads = 8 warps; warp w owns 4 d-cols, lanes sweep K via float4.
__global__ void __cluster_dims__(4, 1, 1) __launch_bounds__(256)
kGemmNorm(const float* __restrict__ outputs,
          const float* __restrict__ W,
          const float* __restrict__ bias) {
    int bg = blockIdx.x >> 2;   // 0..31
    int dg = blockIdx.x & 3;    // 0..3 == cluster rank
    int tid = threadIdx.x, w = tid >> 5, lane = tid & 31;

    __shared__ float so[8][1024];     // K-chunk of the 8 output rows (32 KB)
    __shared__ float semb[8][32];     // emb_raw+bias for our 32 d-cols
    __shared__ float s_partial[8];    // partial sum-of-squares per b
    __shared__ float s_nsq[8];        // full sum-of-squares per b

    int d0 = dg * 32 + w * 4;         // warp's first global d

    float acc[4][8];
#pragma unroll
    for (int dd = 0; dd < 4; dd++)
#pragma unroll
        for (int bb = 0; bb < 8; bb++) acc[dd][bb] = 0.0f;

    const float4* o4 = (const float4*)outputs;
    const float4* w4 = (const float4*)W;

#pragma unroll
    for (int chunk = 0; chunk < 2; chunk++) {
        // stage 8 output rows, k in [chunk*1024, chunk*1024+1024)
        for (int i = tid; i < 8 * 256; i += 256) {
            int bb = i >> 8, c = i & 255;
            ((float4*)so[bb])[c] =
                o4[(size_t)(bg * 8 + bb) * (DIN_ / 4) + chunk * 256 + c];
        }
        __syncthreads();

#pragma unroll
        for (int it = 0; it < 8; it++) {
            int kl = it * 128 + lane * 4;                 // local k in chunk
            int kg4 = (chunk * 1024 + kl) >> 2;           // float4 idx in W row
            float4 wv[4];
#pragma unroll
            for (int dd = 0; dd < 4; dd++)
                wv[dd] = w4[(size_t)(d0 + dd) * (DIN_ / 4) + kg4];
#pragma unroll
            for (int bb = 0; bb < 8; bb++) {
                float4 ov = ((const float4*)so[bb])[it * 32 + lane];
#pragma unroll
                for (int dd = 0; dd < 4; dd++) {
                    float a = acc[dd][bb];
                    a = fmaf(wv[dd].x, ov.x, a);
                    a = fmaf(wv[dd].y, ov.y, a);
                    a = fmaf(wv[dd].z, ov.z, a);
                    a = fmaf(wv[dd].w, ov.w, a);
                    acc[dd][bb] = a;
                }
            }
        }
        __syncthreads();
    }

    // butterfly-reduce each accumulator across the warp; lane dd*8+bb keeps it
    float mine = 0.0f;
#pragma unroll
    for (int dd = 0; dd < 4; dd++)
#pragma unroll
        for (int bb = 0; bb < 8; bb++) {
            float r = acc[dd][bb];
#pragma unroll
            for (int o = 16; o; o >>= 1) r += __shfl_xor_sync(FULL, r, o);
            if (lane == dd * 8 + bb) mine = r;
        }
    int dloc = w * 4 + (lane >> 3);   // 0..31 (local d within this block)
    int bloc = lane & 7;              // 0..7
    mine += bias[dg * 32 + dloc];
    semb[bloc][dloc] = mine;
    __syncthreads();

    // partial sum-of-squares: warp w reduces b-row w
    {
        float v = semb[w][lane];
        float ss = v * v;
#pragma unroll
        for (int o = 16; o; o >>= 1) ss += __shfl_xor_sync(FULL, ss, o);
        if (lane == 0) s_partial[w] = ss;
    }
    cluster_sync_();

    // combine 4 cluster ranks' partials via DSMEM
    if (tid < 8) {
        unsigned sp = (unsigned)__cvta_generic_to_shared(s_partial) + tid * 4;
        float nsq = 0.0f;
#pragma unroll
        for (unsigned rr = 0; rr < 4; rr++)
            nsq += ld_shared_cluster_f32_(mapa_shared_(sp, rr));
        s_nsq[tid] = nsq;
    }
    __syncthreads();

    // normalize + write our d-slice of g_emb
    {
        int b = tid & 7, dl = tid >> 3;   // dl 0..31
        float inv = 1.0f / fmaxf(sqrtf(s_nsq[b]), 1e-12f);
        ((float*)g_emb)[(size_t)(bg * 8 + b) * D_ + dg * 32 + dl] =
            semb[b][dl] * inv;
    }
    if (blockIdx.x == 0 && tid == 0) { g_acc[0] = 0.0f; g_acc[1] = 0.0f; }
    cluster_sync_();   // keep smem alive until all peers finished reading
}

// ---------------- B: main gather + logsumexp + losses + entries --------------
// One block per batch row. 16 warps; warp w handles negs [w*256, w*256+256).
__global__ void __launch_bounds__(512, 2) kMain(
    const float* __restrict__ mbank,
    const int*   __restrict__ indices,
    const int*   __restrict__ ridx,
    float*       __restrict__ out) {
    int b = blockIdx.x;
    int tid = threadIdx.x, w = tid >> 5, lane = tid & 31;

    __shared__ float sneg[M_];
    __shared__ float sr[33];

    float4 e = g_emb[b * 32 + lane];
    const float4* mb4 = (const float4*)mbank;
    const int* ri = ridx + (size_t)b * M_;

    // ---- gather + dot: 256 negs per warp ----
    int m0 = w * 256;
    for (int mb_ = m0; mb_ < m0 + 256; mb_ += 32) {
        int myIdx = ri[mb_ + lane];
#pragma unroll 8
        for (int j = 0; j < 32; j++) {
            int idx = __shfl_sync(FULL, myIdx, j);
            float4 v = mb4[(size_t)idx * 32 + lane];
            float d = v.x * e.x + v.y * e.y;
            d = fmaf(v.z, e.z, d);
            d = fmaf(v.w, e.w, d);
#pragma unroll
            for (int o = 16; o; o >>= 1) d += __shfl_xor_sync(FULL, d, o);
            if (lane == j) sneg[mb_ + j] = d * TAU_INV;
        }
    }
    __syncthreads();

    // ---- each thread owns 8 negs (stride 512, conflict-free) ----
    float vl[8];
    float mx = -3.0e38f;
#pragma unroll
    for (int i = 0; i < 8; i++) {
        vl[i] = sneg[tid + i * 512];
        mx = fmaxf(mx, vl[i]);
    }
#pragma unroll
    for (int o = 16; o; o >>= 1) mx = fmaxf(mx, __shfl_xor_sync(FULL, mx, o));
    if (lane == 0) sr[w] = mx;
    __syncthreads();
    if (w == 0) {
        float t2 = sr[lane & 15];
#pragma unroll
        for (int o = 8; o; o >>= 1) t2 = fmaxf(t2, __shfl_xor_sync(FULL, t2, o));
        if (lane == 0) sr[32] = t2;
    }
    __syncthreads();
    float Mx = sr[32];

    float se = 0.f;
#pragma unroll
    for (int i = 0; i < 8; i++) se += __expf(vl[i] - Mx);
#pragma unroll
    for (int o = 16; o; o >>= 1) se += __shfl_xor_sync(FULL, se, o);
    __syncthreads();
    if (lane == 0) sr[w] = se;
    __syncthreads();
    if (w == 0) {
        float t2 = (lane < 16) ? sr[lane] : 0.f;
#pragma unroll
        for (int o = 8; o; o >>= 1) t2 += __shfl_xor_sync(FULL, t2, o);
        if (lane == 0) sr[32] = Mx + __logf(t2);
    }
    __syncthreads();
    float logC = sr[32];

    // noise loss: sum softplus(neg - logC)
    float ns = 0.f;
#pragma unroll
    for (int i = 0; i < 8; i++) {
        float x = vl[i] - logC;
        ns += (x > 15.f) ? x : log1pf(__expf(x));
    }
#pragma unroll
    for (int o = 16; o; o >>= 1) ns += __shfl_xor_sync(FULL, ns, o);
    __syncthreads();
    if (lane == 0) sr[w] = ns;
    __syncthreads();
    if (w == 0) {
        float t2 = (lane < 16) ? sr[lane] : 0.f;
#pragma unroll
        for (int o = 8; o; o >>= 1) t2 += __shfl_xor_sync(FULL, t2, o);
        if (lane == 0) atomicAdd(&g_acc[1], t2);
    }

    // ---- warp 0: positive term + entries ----
    if (w == 0) {
        int pidx = indices[b];
        float4 p = mb4[(size_t)pidx * 32 + lane];
        float d = p.x * e.x + p.y * e.y;
        d = fmaf(p.z, e.z, d);
        d = fmaf(p.w, e.w, d);
#pragma unroll
        for (int o = 16; o; o >>= 1) d += __shfl_xor_sync(FULL, d, o);
        float pos = d * TAU_INV;

        float4 ent;
        ent.x = 0.5f * (p.x + e.x);
        ent.y = 0.5f * (p.y + e.y);
        ent.z = 0.5f * (p.z + e.z);
        ent.w = 0.5f * (p.w + e.w);
        float nsq = ent.x * ent.x + ent.y * ent.y + ent.z * ent.z + ent.w * ent.w;
#pragma unroll
        for (int o = 16; o; o >>= 1) nsq += __shfl_xor_sync(FULL, nsq, o);
        float inv = 1.0f / fmaxf(sqrtf(nsq), 1e-12f);
        ent.x *= inv; ent.y *= inv; ent.z *= inv; ent.w *= inv;

        int base = 1 + b * D_ + lane * 4;
        out[base + 0] = ent.x;
        out[base + 1] = ent.y;
        out[base + 2] = ent.z;
        out[base + 3] = ent.w;

        if (lane == 0) {
            float x = logC - pos;
            float dl = (x > 15.f) ? x : log1pf(__expf(x));
            atomicAdd(&g_acc[0], dl);
        }
    }
}

// ---------------- C: finalize scalars ----------------------------------------
__global__ void kFinal(float* __restrict__ out) {
    float dl = g_acc[0] * (1.0f / (float)B_);
    float nl = g_acc[1] * (1.0f / (float)B_);
    out[0] = dl + nl;
    out[1 + B_ * D_]     = dl;
    out[1 + B_ * D_ + 1] = nl;
}

// ---------------- launcher ----------------------------------------------------
extern "C" void kernel_launch(void* const* d_in, const int* in_sizes, int n_in,
                              void* d_out, int out_size) {
    const float* outputs = (const float*)d_in[0];
    const float* W       = (const float*)d_in[1];
    const float* bias    = (const float*)d_in[2];
    const float* mbank   = (const float*)d_in[3];
    const int*   indices = (const int*)d_in[4];
    const int*   ridx    = (const int*)d_in[5];
    float* out = (float*)d_out;

    kGemmNorm<<<128, 256>>>(outputs, W, bias);
    kMain<<<256, 512>>>(mbank, indices, ridx, out);
    kFinal<<<1, 1>>>(out);
}

// round 4
// speedup vs baseline: 1.1204x; 1.0209x over previous
#include <cuda_runtime.h>
#include <cstdint>
#include <math.h>

#define FULL 0xffffffffu

static constexpr int B_   = 256;
static constexpr int D_   = 128;
static constexpr int DIN_ = 2048;
static constexpr int M_   = 4096;
static constexpr float TAU_INV = 1.0f / 0.07f;

// ---------------- device scratch ----------------
__device__ float4 g_emb[B_ * (D_ / 4)];   // normalized embeddings, 128 KB
__device__ float  g_acc[2];               // [0]=sum data softplus, [1]=sum noise softplus

// ---------------- cluster helpers (raw PTX, sm_90+) ----------------
__device__ __forceinline__ void cluster_sync_() {
    asm volatile("barrier.cluster.arrive.aligned;" ::: "memory");
    asm volatile("barrier.cluster.wait.aligned;" ::: "memory");
}
__device__ __forceinline__ unsigned mapa_shared_(unsigned smem_addr, unsigned rank) {
    unsigned r;
    asm("mapa.shared::cluster.u32 %0, %1, %2;" : "=r"(r) : "r"(smem_addr), "r"(rank));
    return r;
}
__device__ __forceinline__ float ld_shared_cluster_f32_(unsigned addr) {
    float v;
    asm volatile("ld.shared::cluster.f32 %0, [%1];" : "=f"(v) : "r"(addr));
    return v;
}

// ---------------- A: fused GEMM + bias + L2-normalize (one kernel) ----------
// grid 128 = 32 b-groups (8 rows) x 4 d-groups (32 cols), cluster of 4 over d.
// 512 threads = 16 warps; warp w owns 2 d-cols, lanes sweep K via float4.
__global__ void __cluster_dims__(4, 1, 1) __launch_bounds__(512)
kGemmNorm(const float* __restrict__ outputs,
          const float* __restrict__ W,
          const float* __restrict__ bias) {
    int bg = blockIdx.x >> 2;   // 0..31
    int dg = blockIdx.x & 3;    // 0..3 == cluster rank
    int tid = threadIdx.x, w = tid >> 5, lane = tid & 31;

    __shared__ float so[8][1024];     // K-chunk of the 8 output rows (32 KB)
    __shared__ float semb[8][32];     // emb_raw+bias for our 32 d-cols
    __shared__ float s_partial[8];    // partial sum-of-squares per b
    __shared__ float s_nsq[8];        // full sum-of-squares per b

    int d0 = dg * 32 + w * 2;         // warp's first global d (owns d0, d0+1)

    float acc[2][8];
#pragma unroll
    for (int dd = 0; dd < 2; dd++)
#pragma unroll
        for (int bb = 0; bb < 8; bb++) acc[dd][bb] = 0.0f;

    const float4* o4 = (const float4*)outputs;
    const float4* w4 = (const float4*)W;

#pragma unroll
    for (int chunk = 0; chunk < 2; chunk++) {
        // stage 8 output rows, k in [chunk*1024, chunk*1024+1024)
        for (int i = tid; i < 8 * 256; i += 512) {
            int bb = i >> 8, c = i & 255;
            ((float4*)so[bb])[c] =
                o4[(size_t)(bg * 8 + bb) * (DIN_ / 4) + chunk * 256 + c];
        }
        __syncthreads();

#pragma unroll
        for (int it = 0; it < 8; it++) {
            int kg4 = (chunk * 1024 + it * 128) / 4 + lane;  // float4 idx in W row
            float4 wv[2];
#pragma unroll
            for (int dd = 0; dd < 2; dd++)
                wv[dd] = w4[(size_t)(d0 + dd) * (DIN_ / 4) + kg4];
#pragma unroll
            for (int bb = 0; bb < 8; bb++) {
                float4 ov = ((const float4*)so[bb])[it * 32 + lane];
#pragma unroll
                for (int dd = 0; dd < 2; dd++) {
                    float a = acc[dd][bb];
                    a = fmaf(wv[dd].x, ov.x, a);
                    a = fmaf(wv[dd].y, ov.y, a);
                    a = fmaf(wv[dd].z, ov.z, a);
                    a = fmaf(wv[dd].w, ov.w, a);
                    acc[dd][bb] = a;
                }
            }
        }
        __syncthreads();
    }

    // butterfly-reduce each of the 16 accumulators; lane dd*8+bb keeps it
    float mine = 0.0f;
#pragma unroll
    for (int dd = 0; dd < 2; dd++)
#pragma unroll
        for (int bb = 0; bb < 8; bb++) {
            float r = acc[dd][bb];
#pragma unroll
            for (int o = 16; o; o >>= 1) r += __shfl_xor_sync(FULL, r, o);
            if (lane == dd * 8 + bb) mine = r;
        }
    if (lane < 16) {
        int dd = lane >> 3, bloc = lane & 7;
        int dloc = w * 2 + dd;                 // 0..31 local d
        semb[bloc][dloc] = mine + bias[dg * 32 + dloc];
    }
    __syncthreads();

    // partial sum-of-squares: warp w (<8) reduces b-row w
    if (w < 8) {
        float v = semb[w][lane];
        float ss = v * v;
#pragma unroll
        for (int o = 16; o; o >>= 1) ss += __shfl_xor_sync(FULL, ss, o);
        if (lane == 0) s_partial[w] = ss;
    }
    cluster_sync_();

    // combine 4 cluster ranks' partials via DSMEM
    if (tid < 8) {
        unsigned sp = (unsigned)__cvta_generic_to_shared(s_partial) + tid * 4;
        float nsq = 0.0f;
#pragma unroll
        for (unsigned rr = 0; rr < 4; rr++)
            nsq += ld_shared_cluster_f32_(mapa_shared_(sp, rr));
        s_nsq[tid] = nsq;
    }
    __syncthreads();

    // normalize + write our d-slice of g_emb (256 threads cover 8b x 32d)
    if (tid < 256) {
        int b = tid & 7, dl = tid >> 3;   // dl 0..31
        float inv = 1.0f / fmaxf(sqrtf(s_nsq[b]), 1e-12f);
        ((float*)g_emb)[(size_t)(bg * 8 + b) * D_ + dg * 32 + dl] =
            semb[b][dl] * inv;
    }
    if (blockIdx.x == 0 && tid == 0) { g_acc[0] = 0.0f; g_acc[1] = 0.0f; }
    cluster_sync_();   // keep smem alive until all peers finished reading
}

// ---------------- B: main gather + logsumexp + losses + entries --------------
// One block per batch row. 16 warps; warp w handles negs [w*256, w*256+256).
__global__ void __launch_bounds__(512, 2) kMain(
    const float* __restrict__ mbank,
    const int*   __restrict__ indices,
    const int*   __restrict__ ridx,
    float*       __restrict__ out) {
    int b = blockIdx.x;
    int tid = threadIdx.x, w = tid >> 5, lane = tid & 31;

    __shared__ float sneg[M_];
    __shared__ float sr[33];

    float4 e = g_emb[b * 32 + lane];
    const float4* mb4 = (const float4*)mbank;
    const int* ri = ridx + (size_t)b * M_;

    // ---- gather + dot: 256 negs per warp ----
    int m0 = w * 256;
    for (int mb_ = m0; mb_ < m0 + 256; mb_ += 32) {
        int myIdx = ri[mb_ + lane];
#pragma unroll 8
        for (int j = 0; j < 32; j++) {
            int idx = __shfl_sync(FULL, myIdx, j);
            float4 v = mb4[(size_t)idx * 32 + lane];
            float d = v.x * e.x + v.y * e.y;
            d = fmaf(v.z, e.z, d);
            d = fmaf(v.w, e.w, d);
#pragma unroll
            for (int o = 16; o; o >>= 1) d += __shfl_xor_sync(FULL, d, o);
            if (lane == j) sneg[mb_ + j] = d * TAU_INV;
        }
    }
    __syncthreads();

    // ---- each thread owns 8 negs (stride 512, conflict-free) ----
    float vl[8];
    float mx = -3.0e38f;
#pragma unroll
    for (int i = 0; i < 8; i++) {
        vl[i] = sneg[tid + i * 512];
        mx = fmaxf(mx, vl[i]);
    }
#pragma unroll
    for (int o = 16; o; o >>= 1) mx = fmaxf(mx, __shfl_xor_sync(FULL, mx, o));
    if (lane == 0) sr[w] = mx;
    __syncthreads();
    if (w == 0) {
        float t2 = sr[lane & 15];
#pragma unroll
        for (int o = 8; o; o >>= 1) t2 = fmaxf(t2, __shfl_xor_sync(FULL, t2, o));
        if (lane == 0) sr[32] = t2;
    }
    __syncthreads();
    float Mx = sr[32];

    float se = 0.f;
#pragma unroll
    for (int i = 0; i < 8; i++) se += __expf(vl[i] - Mx);
#pragma unroll
    for (int o = 16; o; o >>= 1) se += __shfl_xor_sync(FULL, se, o);
    __syncthreads();
    if (lane == 0) sr[w] = se;
    __syncthreads();
    if (w == 0) {
        float t2 = (lane < 16) ? sr[lane] : 0.f;
#pragma unroll
        for (int o = 8; o; o >>= 1) t2 += __shfl_xor_sync(FULL, t2, o);
        if (lane == 0) sr[32] = Mx + __logf(t2);
    }
    __syncthreads();
    float logC = sr[32];

    // noise loss: sum softplus(neg - logC)
    float ns = 0.f;
#pragma unroll
    for (int i = 0; i < 8; i++) {
        float x = vl[i] - logC;
        ns += (x > 15.f) ? x : log1pf(__expf(x));
    }
#pragma unroll
    for (int o = 16; o; o >>= 1) ns += __shfl_xor_sync(FULL, ns, o);
    __syncthreads();
    if (lane == 0) sr[w] = ns;
    __syncthreads();
    if (w == 0) {
        float t2 = (lane < 16) ? sr[lane] : 0.f;
#pragma unroll
        for (int o = 8; o; o >>= 1) t2 += __shfl_xor_sync(FULL, t2, o);
        if (lane == 0) atomicAdd(&g_acc[1], t2);
    }

    // ---- warp 0: positive term + entries ----
    if (w == 0) {
        int pidx = indices[b];
        float4 p = mb4[(size_t)pidx * 32 + lane];
        float d = p.x * e.x + p.y * e.y;
        d = fmaf(p.z, e.z, d);
        d = fmaf(p.w, e.w, d);
#pragma unroll
        for (int o = 16; o; o >>= 1) d += __shfl_xor_sync(FULL, d, o);
        float pos = d * TAU_INV;

        float4 ent;
        ent.x = 0.5f * (p.x + e.x);
        ent.y = 0.5f * (p.y + e.y);
        ent.z = 0.5f * (p.z + e.z);
        ent.w = 0.5f * (p.w + e.w);
        float nsq = ent.x * ent.x + ent.y * ent.y + ent.z * ent.z + ent.w * ent.w;
#pragma unroll
        for (int o = 16; o; o >>= 1) nsq += __shfl_xor_sync(FULL, nsq, o);
        float inv = 1.0f / fmaxf(sqrtf(nsq), 1e-12f);
        ent.x *= inv; ent.y *= inv; ent.z *= inv; ent.w *= inv;

        int base = 1 + b * D_ + lane * 4;
        out[base + 0] = ent.x;
        out[base + 1] = ent.y;
        out[base + 2] = ent.z;
        out[base + 3] = ent.w;

        if (lane == 0) {
            float x = logC - pos;
            float dl = (x > 15.f) ? x : log1pf(__expf(x));
            atomicAdd(&g_acc[0], dl);
        }
    }
}

// ---------------- C: finalize scalars ----------------------------------------
__global__ void kFinal(float* __restrict__ out) {
    float dl = g_acc[0] * (1.0f / (float)B_);
    float nl = g_acc[1] * (1.0f / (float)B_);
    out[0] = dl + nl;
    out[1 + B_ * D_]     = dl;
    out[1 + B_ * D_ + 1] = nl;
}

// ---------------- launcher ----------------------------------------------------
extern "C" void kernel_launch(void* const* d_in, const int* in_sizes, int n_in,
                              void* d_out, int out_size) {
    const float* outputs = (const float*)d_in[0];
    const float* W       = (const float*)d_in[1];
    const float* bias    = (const float*)d_in[2];
    const float* mbank   = (const float*)d_in[3];
    const int*   indices = (const int*)d_in[4];
    const int*   ridx    = (const int*)d_in[5];
    float* out = (float*)d_out;

    kGemmNorm<<<128, 512>>>(outputs, W, bias);
    kMain<<<256, 512>>>(mbank, indices, ridx, out);
    kFinal<<<1, 1>>>(out);
}

// round 5
// speedup vs baseline: 1.1344x; 1.0125x over previous
#include <cuda_runtime.h>
#include <cstdint>
#include <math.h>

#define FULL 0xffffffffu

static constexpr int B_   = 256;
static constexpr int D_   = 128;
static constexpr int DIN_ = 2048;
static constexpr int M_   = 4096;
static constexpr float TAU_INV = 1.0f / 0.07f;

// ---------------- device scratch ----------------
__device__ float4 g_emb[B_ * (D_ / 4)];   // normalized embeddings, 128 KB
__device__ float  g_acc[2];               // [0]=sum data softplus, [1]=sum noise softplus
__device__ unsigned g_cnt;                // kMain completion counter

// ---------------- cluster helpers (raw PTX, sm_90+) ----------------
__device__ __forceinline__ void cluster_sync_() {
    asm volatile("barrier.cluster.arrive.aligned;" ::: "memory");
    asm volatile("barrier.cluster.wait.aligned;" ::: "memory");
}
__device__ __forceinline__ unsigned mapa_shared_(unsigned smem_addr, unsigned rank) {
    unsigned r;
    asm("mapa.shared::cluster.u32 %0, %1, %2;" : "=r"(r) : "r"(smem_addr), "r"(rank));
    return r;
}
__device__ __forceinline__ float ld_shared_cluster_f32_(unsigned addr) {
    float v;
    asm volatile("ld.shared::cluster.f32 %0, [%1];" : "=f"(v) : "r"(addr));
    return v;
}

// ---------------- A: fused GEMM + bias + L2-normalize ------------------------
// grid 256 = 64 b-groups (4 rows) x 4 d-groups (32 cols), cluster of 4 over d.
// 512 threads = 16 warps; warp w owns 2 d-cols; 2 blocks/SM for latency hiding.
__global__ void __cluster_dims__(4, 1, 1) __launch_bounds__(512, 2)
kGemmNorm(const float* __restrict__ outputs,
          const float* __restrict__ W,
          const float* __restrict__ bias) {
    int bg = blockIdx.x >> 2;   // 0..63
    int dg = blockIdx.x & 3;    // 0..3 == cluster rank
    int tid = threadIdx.x, w = tid >> 5, lane = tid & 31;

    __shared__ float so[4][1024];     // K-chunk of the 4 output rows (16 KB)
    __shared__ float semb[4][32];     // emb_raw+bias for our 32 d-cols
    __shared__ float s_partial[4];    // partial sum-of-squares per b
    __shared__ float s_nsq[4];        // full sum-of-squares per b

    int d0 = dg * 32 + w * 2;         // warp's first global d (owns d0, d0+1)

    float acc[2][4];
#pragma unroll
    for (int dd = 0; dd < 2; dd++)
#pragma unroll
        for (int bb = 0; bb < 4; bb++) acc[dd][bb] = 0.0f;

    const float4* o4 = (const float4*)outputs;
    const float4* w4 = (const float4*)W;

#pragma unroll
    for (int chunk = 0; chunk < 2; chunk++) {
        // stage 4 output rows, k in [chunk*1024, chunk*1024+1024)
        for (int i = tid; i < 4 * 256; i += 512) {
            int bb = i >> 8, c = i & 255;
            ((float4*)so[bb])[c] =
                o4[(size_t)(bg * 4 + bb) * (DIN_ / 4) + chunk * 256 + c];
        }
        __syncthreads();

#pragma unroll
        for (int it = 0; it < 8; it++) {
            int kg4 = (chunk * 1024 + it * 128) / 4 + lane;  // float4 idx in W row
            float4 wv[2];
#pragma unroll
            for (int dd = 0; dd < 2; dd++)
                wv[dd] = w4[(size_t)(d0 + dd) * (DIN_ / 4) + kg4];
#pragma unroll
            for (int bb = 0; bb < 4; bb++) {
                float4 ov = ((const float4*)so[bb])[it * 32 + lane];
#pragma unroll
                for (int dd = 0; dd < 2; dd++) {
                    float a = acc[dd][bb];
                    a = fmaf(wv[dd].x, ov.x, a);
                    a = fmaf(wv[dd].y, ov.y, a);
                    a = fmaf(wv[dd].z, ov.z, a);
                    a = fmaf(wv[dd].w, ov.w, a);
                    acc[dd][bb] = a;
                }
            }
        }
        __syncthreads();
    }

    // butterfly-reduce each of the 8 accumulators; lane dd*4+bb keeps it
    float mine = 0.0f;
#pragma unroll
    for (int dd = 0; dd < 2; dd++)
#pragma unroll
        for (int bb = 0; bb < 4; bb++) {
            float r = acc[dd][bb];
#pragma unroll
            for (int o = 16; o; o >>= 1) r += __shfl_xor_sync(FULL, r, o);
            if (lane == dd * 4 + bb) mine = r;
        }
    if (lane < 8) {
        int dd = lane >> 2, bloc = lane & 3;
        int dloc = w * 2 + dd;                 // 0..31 local d
        semb[bloc][dloc] = mine + bias[dg * 32 + dloc];
    }
    __syncthreads();

    // partial sum-of-squares: warp w (<4) reduces b-row w
    if (w < 4) {
        float v = semb[w][lane];
        float ss = v * v;
#pragma unroll
        for (int o = 16; o; o >>= 1) ss += __shfl_xor_sync(FULL, ss, o);
        if (lane == 0) s_partial[w] = ss;
    }
    cluster_sync_();

    // combine 4 cluster ranks' partials via DSMEM
    if (tid < 4) {
        unsigned sp = (unsigned)__cvta_generic_to_shared(s_partial) + tid * 4;
        float nsq = 0.0f;
#pragma unroll
        for (unsigned rr = 0; rr < 4; rr++)
            nsq += ld_shared_cluster_f32_(mapa_shared_(sp, rr));
        s_nsq[tid] = nsq;
    }
    __syncthreads();

    // normalize + write our d-slice of g_emb (128 threads cover 4b x 32d)
    if (tid < 128) {
        int b = tid & 3, dl = tid >> 2;   // dl 0..31
        float inv = 1.0f / fmaxf(sqrtf(s_nsq[b]), 1e-12f);
        ((float*)g_emb)[(size_t)(bg * 4 + b) * D_ + dg * 32 + dl] =
            semb[b][dl] * inv;
    }
    if (blockIdx.x == 0 && tid == 0) {
        g_acc[0] = 0.0f; g_acc[1] = 0.0f; g_cnt = 0u;
    }
    cluster_sync_();   // keep smem alive until all peers finished reading
}

// ---------------- B: main gather + logsumexp + losses + entries + finalize ---
// One block per batch row. 16 warps; warp w handles negs [w*256, w*256+256).
__global__ void __launch_bounds__(512, 2) kMain(
    const float* __restrict__ mbank,
    const int*   __restrict__ indices,
    const int*   __restrict__ ridx,
    float*       __restrict__ out) {
    int b = blockIdx.x;
    int tid = threadIdx.x, w = tid >> 5, lane = tid & 31;

    __shared__ float sneg[M_];
    __shared__ float sr[33];

    float4 e = g_emb[b * 32 + lane];
    const float4* mb4 = (const float4*)mbank;
    const int* ri = ridx + (size_t)b * M_;

    // ---- gather + dot: 256 negs per warp ----
    int m0 = w * 256;
    for (int mb_ = m0; mb_ < m0 + 256; mb_ += 32) {
        int myIdx = ri[mb_ + lane];
#pragma unroll 8
        for (int j = 0; j < 32; j++) {
            int idx = __shfl_sync(FULL, myIdx, j);
            float4 v = mb4[(size_t)idx * 32 + lane];
            float d = v.x * e.x + v.y * e.y;
            d = fmaf(v.z, e.z, d);
            d = fmaf(v.w, e.w, d);
#pragma unroll
            for (int o = 16; o; o >>= 1) d += __shfl_xor_sync(FULL, d, o);
            if (lane == j) sneg[mb_ + j] = d * TAU_INV;
        }
    }
    __syncthreads();

    // ---- each thread owns 8 negs (stride 512, conflict-free) ----
    float vl[8];
    float mx = -3.0e38f;
#pragma unroll
    for (int i = 0; i < 8; i++) {
        vl[i] = sneg[tid + i * 512];
        mx = fmaxf(mx, vl[i]);
    }
#pragma unroll
    for (int o = 16; o; o >>= 1) mx = fmaxf(mx, __shfl_xor_sync(FULL, mx, o));
    if (lane == 0) sr[w] = mx;
    __syncthreads();
    if (w == 0) {
        float t2 = sr[lane & 15];
#pragma unroll
        for (int o = 8; o; o >>= 1) t2 = fmaxf(t2, __shfl_xor_sync(FULL, t2, o));
        if (lane == 0) sr[32] = t2;
    }
    __syncthreads();
    float Mx = sr[32];

    float se = 0.f;
#pragma unroll
    for (int i = 0; i < 8; i++) se += __expf(vl[i] - Mx);
#pragma unroll
    for (int o = 16; o; o >>= 1) se += __shfl_xor_sync(FULL, se, o);
    __syncthreads();
    if (lane == 0) sr[w] = se;
    __syncthreads();
    if (w == 0) {
        float t2 = (lane < 16) ? sr[lane] : 0.f;
#pragma unroll
        for (int o = 8; o; o >>= 1) t2 += __shfl_xor_sync(FULL, t2, o);
        if (lane == 0) sr[32] = Mx + __logf(t2);
    }
    __syncthreads();
    float logC = sr[32];

    // noise loss: sum softplus(neg - logC)
    float ns = 0.f;
#pragma unroll
    for (int i = 0; i < 8; i++) {
        float x = vl[i] - logC;
        ns += (x > 15.f) ? x : log1pf(__expf(x));
    }
#pragma unroll
    for (int o = 16; o; o >>= 1) ns += __shfl_xor_sync(FULL, ns, o);
    __syncthreads();
    if (lane == 0) sr[w] = ns;
    __syncthreads();
    if (w == 0) {
        float t2 = (lane < 16) ? sr[lane] : 0.f;
#pragma unroll
        for (int o = 8; o; o >>= 1) t2 += __shfl_xor_sync(FULL, t2, o);
        if (lane == 0) atomicAdd(&g_acc[1], t2);
    }

    // ---- warp 0: positive term + entries + finalize ----
    if (w == 0) {
        int pidx = indices[b];
        float4 p = mb4[(size_t)pidx * 32 + lane];
        float d = p.x * e.x + p.y * e.y;
        d = fmaf(p.z, e.z, d);
        d = fmaf(p.w, e.w, d);
#pragma unroll
        for (int o = 16; o; o >>= 1) d += __shfl_xor_sync(FULL, d, o);
        float pos = d * TAU_INV;

        float4 ent;
        ent.x = 0.5f * (p.x + e.x);
        ent.y = 0.5f * (p.y + e.y);
        ent.z = 0.5f * (p.z + e.z);
        ent.w = 0.5f * (p.w + e.w);
        float nsq = ent.x * ent.x + ent.y * ent.y + ent.z * ent.z + ent.w * ent.w;
#pragma unroll
        for (int o = 16; o; o >>= 1) nsq += __shfl_xor_sync(FULL, nsq, o);
        float inv = 1.0f / fmaxf(sqrtf(nsq), 1e-12f);
        ent.x *= inv; ent.y *= inv; ent.z *= inv; ent.w *= inv;

        int base = 1 + b * D_ + lane * 4;
        out[base + 0] = ent.x;
        out[base + 1] = ent.y;
        out[base + 2] = ent.z;
        out[base + 3] = ent.w;

        if (lane == 0) {
            float x = logC - pos;
            float dl = (x > 15.f) ? x : log1pf(__expf(x));
            atomicAdd(&g_acc[0], dl);
            __threadfence();
            unsigned t = atomicAdd(&g_cnt, 1u);
            if (t == (unsigned)(B_ - 1)) {     // last block finalizes scalars
                float dsum = g_acc[0] * (1.0f / (float)B_);
                float nsum = g_acc[1] * (1.0f / (float)B_);
                out[0] = dsum + nsum;
                out[1 + B_ * D_]     = dsum;
                out[1 + B_ * D_ + 1] = nsum;
            }
        }
    }
}

// ---------------- launcher ----------------------------------------------------
extern "C" void kernel_launch(void* const* d_in, const int* in_sizes, int n_in,
                              void* d_out, int out_size) {
    const float* outputs = (const float*)d_in[0];
    const float* W       = (const float*)d_in[1];
    const float* bias    = (const float*)d_in[2];
    const float* mbank   = (const float*)d_in[3];
    const int*   indices = (const int*)d_in[4];
    const int*   ridx    = (const int*)d_in[5];
    float* out = (float*)d_out;

    kGemmNorm<<<256, 512>>>(outputs, W, bias);
    kMain<<<256, 512>>>(mbank, indices, ridx, out);
}